// round 13
// baseline (speedup 1.0000x reference)
#include <cuda_runtime.h>
#include <cuda_bf16.h>
#include <cstdint>

#define NE    1024
#define H     128
#define B_MAX 16384

// ---------------------------------------------------------------------------
// Device scratch (no allocation allowed)
// W split into bf16 hi/lo, pre-swizzled SW64 chunk tiles:
// 32 K-chunks, each [128 n-rows x 32 k] bf16 = 128 x 64B = 8192 B.
// ---------------------------------------------------------------------------
__device__ __align__(16) unsigned char g_Whi[32 * 8192];
__device__ __align__(16) unsigned char g_Wlo[32 * 8192];

// ---------------------------------------------------------------------------
__device__ __forceinline__ unsigned smem_u32(const void* p) {
    unsigned a;
    asm("{ .reg .u64 t; cvta.to.shared.u64 t, %1; cvt.u32.u64 %0, t; }"
        : "=r"(a) : "l"(p));
    return a;
}
__device__ __host__ __forceinline__ unsigned sw64(unsigned o) {
    return o ^ ((o >> 3) & 0x30);
}

// split fp32x4 -> bf16 hi (packed u64) + bf16 lo (packed u64)
__device__ __forceinline__ void split4(float4 v, unsigned long long& hi,
                                       unsigned long long& lo) {
    __nv_bfloat162 a = __float22bfloat162_rn(make_float2(v.x, v.y));
    __nv_bfloat162 b = __float22bfloat162_rn(make_float2(v.z, v.w));
    float rx = v.x - __bfloat162float(a.x);
    float ry = v.y - __bfloat162float(a.y);
    float rz = v.z - __bfloat162float(b.x);
    float rw = v.w - __bfloat162float(b.y);
    __nv_bfloat162 c = __float22bfloat162_rn(make_float2(rx, ry));
    __nv_bfloat162 d = __float22bfloat162_rn(make_float2(rz, rw));
    unsigned ua = *reinterpret_cast<unsigned*>(&a);
    unsigned ub = *reinterpret_cast<unsigned*>(&b);
    unsigned uc = *reinterpret_cast<unsigned*>(&c);
    unsigned ud = *reinterpret_cast<unsigned*>(&d);
    hi = (unsigned long long)ua | ((unsigned long long)ub << 32);
    lo = (unsigned long long)uc | ((unsigned long long)ud << 32);
}

#define LDMX4(r0, r1, r2, r3, addr)                                          \
    asm volatile("ldmatrix.sync.aligned.m8n8.x4.shared.b16 {%0,%1,%2,%3}, [%4];" \
                 : "=r"(r0), "=r"(r1), "=r"(r2), "=r"(r3) : "r"(addr))

#define MMA16816(c, a0, a1, a2, a3, b0, b1)                                  \
    asm volatile("mma.sync.aligned.m16n8k16.row.col.f32.bf16.bf16.f32 "      \
                 "{%0,%1,%2,%3}, {%4,%5,%6,%7}, {%8,%9}, {%0,%1,%2,%3};"     \
                 : "+f"((c)[0]), "+f"((c)[1]), "+f"((c)[2]), "+f"((c)[3])    \
                 : "r"(a0), "r"(a1), "r"(a2), "r"(a3), "r"(b0), "r"(b1))

#define CP_ASYNC16(dst, src)                                                 \
    asm volatile("cp.async.cg.shared.global [%0], [%1], 16;"                 \
                 :: "r"(dst), "l"(src))

// ---------------------------------------------------------------------------
// Prep: W [128,1024] fp32 -> g_Whi/g_Wlo SW64-swizzled bf16 chunk tiles
// ---------------------------------------------------------------------------
__global__ void prep_w_kernel(const float* __restrict__ W) {
    int idx = blockIdx.x * 256 + threadIdx.x;   // 0..32767
    int h   = idx >> 8;
    int c4g = idx & 255;
    float4 v = *(const float4*)(W + (size_t)h * NE + c4g * 4);
    unsigned long long hi, lo;
    split4(v, hi, lo);
    int kc = c4g >> 3;          // K-chunk (32 wide)
    int c4 = c4g & 7;           // float4 within chunk
    unsigned dst = (unsigned)kc * 8192u + sw64((unsigned)(h * 64 + c4 * 8));
    *reinterpret_cast<unsigned long long*>(g_Whi + dst) = hi;
    *reinterpret_cast<unsigned long long*>(g_Wlo + dst) = lo;
}

// ---------------------------------------------------------------------------
// Fused kernel (3 CTAs/SM).
// Phase 1 (GEMM): 64 rows (= 32 b x {values,mask}) x 128 cols via mma.sync,
//   split bf16 (acc += Ahi*Bhi + Ahi*Blo + Alo*Bhi), K chunks of 32,
//   double-buffered cp.async for W, LDG->split->swizzled STS for x.
// Phase 2 (head): same CTA consumes its 32 b's from smem:
//   out[b,k] = sum_h values[b,h] * exp(mask[b,h]*cov[h,k]) / Z[b,h] + bias[k]
//   cov cached in smem as bf16, row stride 160 bf16 (80 words == 16 mod 32
//   -> the 4 h-groups of a warp hit complementary bank halves: 2-phase LDS.64).
//
// SMEM (bytes):
//   [0, 49152)      gemm staging (A: 2 stages x 8KB, B: 2 stages x 16KB)
//   [0, 33792)      reused after mainloop as vm[64][132] fp32
//   [33792, 74752)  cov bf16 [128][stride 160]
// ---------------------------------------------------------------------------
#define FUSED_SMEM 74752
#define VM_PAD 132
#define COVW 80   // cov row stride in 32-bit words (160 bf16)

__global__ __launch_bounds__(256, 3)
void fused_kernel(const float* __restrict__ x, const float* __restrict__ cov,
                  const float* __restrict__ bias, float* __restrict__ out)
{
    extern __shared__ unsigned char sm[];
    float* smf = reinterpret_cast<float*>(sm);
    const unsigned smb = smem_u32(sm);

    const int tid  = threadIdx.x;
    const int wid  = tid >> 5, lane = tid & 31;
    const int warp_m = wid & 3, warp_n = wid >> 2;
    const int m_base = warp_m * 16, n_base = warp_n * 64;
    const int r0 = blockIdx.x * 64;

    // ---- per-lane ldmatrix offsets
    const int lrow8 = (lane & 7) + ((lane >> 3) & 1) * 8;
    const int ksel  = lane >> 4;
    const unsigned aoff0 = sw64((unsigned)((m_base + lrow8) * 64 + ksel * 16));
    const unsigned aoff1 = sw64((unsigned)((m_base + lrow8) * 64 + 32 + ksel * 16));
    unsigned boff[4][2];
#pragma unroll
    for (int p = 0; p < 4; p++) {
        unsigned rb = (unsigned)(n_base + p * 16 + lrow8) * 64 + ksel * 16;
#pragma unroll
        for (int kk = 0; kk < 2; kk++) boff[p][kk] = sw64(rb + kk * 32);
    }

    // ---- x staging map: 2 float4 per thread
    const int xrow = tid >> 3;
    const int xc4  = tid & 7;
    const unsigned asw0 = sw64((unsigned)(xrow * 64 + xc4 * 8));
    const unsigned asw1 = sw64((unsigned)((xrow + 32) * 64 + xc4 * 8));
    const float* xbase = x + (size_t)r0 * NE + xc4 * 4;

    // ---- W cp.async map
    const unsigned wdst0 = (unsigned)(tid * 16);
    const unsigned wdst1 = (unsigned)(tid * 16 + 4096);

    float acc[8][4];
#pragma unroll
    for (int t = 0; t < 8; t++)
#pragma unroll
        for (int j = 0; j < 4; j++) acc[t][j] = 0.f;

    // prologue
    {
        unsigned bh = smb + 16384, bl = smb + 24576;
        CP_ASYNC16(bh + wdst0, g_Whi + wdst0);
        CP_ASYNC16(bh + wdst1, g_Whi + wdst1);
        CP_ASYNC16(bl + wdst0, g_Wlo + wdst0);
        CP_ASYNC16(bl + wdst1, g_Wlo + wdst1);
        asm volatile("cp.async.commit_group;");
    }
    float4 xv0 = *(const float4*)(xbase + (size_t)xrow * NE);
    float4 xv1 = *(const float4*)(xbase + (size_t)(xrow + 32) * NE);

    for (int kc = 0; kc < 32; kc++) {
        const int s = kc & 1;
        const unsigned Ahi_b = smb + s * 8192;
        const unsigned Alo_b = Ahi_b + 4096;
        const unsigned Bhi_b = smb + 16384 + s * 16384;
        const unsigned Blo_b = Bhi_b + 8192;

        {
            unsigned long long hi, lo;
            split4(xv0, hi, lo);
            *reinterpret_cast<unsigned long long*>(sm + s * 8192 + asw0) = hi;
            *reinterpret_cast<unsigned long long*>(sm + s * 8192 + 4096 + asw0) = lo;
            split4(xv1, hi, lo);
            *reinterpret_cast<unsigned long long*>(sm + s * 8192 + asw1) = hi;
            *reinterpret_cast<unsigned long long*>(sm + s * 8192 + 4096 + asw1) = lo;
        }

        asm volatile("cp.async.wait_group 0;");
        __syncthreads();

        if (kc < 31) {
            const unsigned char* wh = g_Whi + (size_t)(kc + 1) * 8192;
            const unsigned char* wl = g_Wlo + (size_t)(kc + 1) * 8192;
            unsigned bh = smb + 16384 + (s ^ 1) * 16384, bl = bh + 8192;
            CP_ASYNC16(bh + wdst0, wh + wdst0);
            CP_ASYNC16(bh + wdst1, wh + wdst1);
            CP_ASYNC16(bl + wdst0, wl + wdst0);
            CP_ASYNC16(bl + wdst1, wl + wdst1);
            asm volatile("cp.async.commit_group;");
            const float* xs = xbase + (kc + 1) * 32;
            xv0 = *(const float4*)(xs + (size_t)xrow * NE);
            xv1 = *(const float4*)(xs + (size_t)(xrow + 32) * NE);
        }

        // ldmatrix.x4 on B: m0=n0-7/k0-7, m1=n8-15/k0-7, m2=n0-7/k8-15,
        // m3=n8-15/k8-15 -> mma B pairs (m0,m2) and (m1,m3).
#pragma unroll
        for (int kk = 0; kk < 2; kk++) {
            const unsigned ao = kk ? aoff1 : aoff0;
            unsigned ah0, ah1, ah2, ah3, al0, al1, al2, al3;
            LDMX4(ah0, ah1, ah2, ah3, Ahi_b + ao);
            LDMX4(al0, al1, al2, al3, Alo_b + ao);
#pragma unroll
            for (int p = 0; p < 4; p++) {
                unsigned bh0, bh1, bh2, bh3, bl0, bl1, bl2, bl3;
                LDMX4(bh0, bh1, bh2, bh3, Bhi_b + boff[p][kk]);
                LDMX4(bl0, bl1, bl2, bl3, Blo_b + boff[p][kk]);
                MMA16816(acc[2*p],   ah0, ah1, ah2, ah3, bh0, bh2);
                MMA16816(acc[2*p],   ah0, ah1, ah2, ah3, bl0, bl2);
                MMA16816(acc[2*p],   al0, al1, al2, al3, bh0, bh2);
                MMA16816(acc[2*p+1], ah0, ah1, ah2, ah3, bh1, bh3);
                MMA16816(acc[2*p+1], ah0, ah1, ah2, ah3, bl1, bl3);
                MMA16816(acc[2*p+1], al0, al1, al2, al3, bh1, bh3);
            }
        }
        __syncthreads();
    }

    // ---- epilogue: accums -> vm_s[64][VM_PAD] fp32 (rows: m=2*b_local+s)
    {
        const int gid = lane >> 2, tig = lane & 3;
        const int m0 = m_base + gid, m1 = m0 + 8;
#pragma unroll
        for (int nt = 0; nt < 8; nt++) {
            const int col = n_base + nt * 8 + tig * 2;
            *(float2*)(smf + m0 * VM_PAD + col) = make_float2(acc[nt][0], acc[nt][1]);
            *(float2*)(smf + m1 * VM_PAD + col) = make_float2(acc[nt][2], acc[nt][3]);
        }
    }

    // ---- load cov -> smem bf16 [128][COVW words] (disjoint from vm_s)
    {
        const float2* cg = (const float2*)cov;                // 8192 float2
        unsigned* cs = (unsigned*)(smf + 64 * VM_PAD);
#pragma unroll 4
        for (int i = tid; i < (H * H) / 2; i += 256) {
            int h = i >> 6, kp = i & 63;
            __nv_bfloat162 bb = __float22bfloat162_rn(cg[i]);
            cs[h * COVW + kp] = *reinterpret_cast<unsigned*>(&bb);
        }
    }
    __syncthreads();

    // ---- head phase: 8 warps x 4 b each (32 b per CTA)
    const unsigned* cov_s = (const unsigned*)(smf + 64 * VM_PAD);
    const int g = lane >> 3;      // h within group of 4
    const int r = lane & 7;       // lane owns k = w*32 + r*4 + t
    const unsigned* crow_base = cov_s + r * 2;

#pragma unroll 1
    for (int i = 0; i < 4; i++) {
        const int bl = wid * 4 + i;
        const float* vrow = smf + (2 * bl) * VM_PAD;       // values row
        const float* mrow = smf + (2 * bl + 1) * VM_PAD;   // mask row

        float oacc[16];
#pragma unroll
        for (int j = 0; j < 16; j++) oacc[j] = 0.f;

        for (int h0 = 0; h0 < H; h0 += 4) {
            const int h = h0 + g;
            const float tm = mrow[h] * 1.4426950408889634f;   // log2(e)
            const unsigned* crow = crow_base + h * COVW;
            float e[16];
            float Z = 0.f;
#pragma unroll
            for (int w = 0; w < 4; w++) {
                uint2 cp = *(const uint2*)(crow + w * 16);
                float c0 = __uint_as_float(cp.x << 16);
                float c1 = __uint_as_float(cp.x & 0xFFFF0000u);
                float c2 = __uint_as_float(cp.y << 16);
                float c3 = __uint_as_float(cp.y & 0xFFFF0000u);
                float e0, e1, e2, e3;
                asm("ex2.approx.ftz.f32 %0, %1;" : "=f"(e0) : "f"(tm * c0));
                asm("ex2.approx.ftz.f32 %0, %1;" : "=f"(e1) : "f"(tm * c1));
                asm("ex2.approx.ftz.f32 %0, %1;" : "=f"(e2) : "f"(tm * c2));
                asm("ex2.approx.ftz.f32 %0, %1;" : "=f"(e3) : "f"(tm * c3));
                e[w*4+0] = e0; e[w*4+1] = e1; e[w*4+2] = e2; e[w*4+3] = e3;
                Z += (e0 + e1) + (e2 + e3);
            }
            Z += __shfl_xor_sync(0xffffffffu, Z, 1);
            Z += __shfl_xor_sync(0xffffffffu, Z, 2);
            Z += __shfl_xor_sync(0xffffffffu, Z, 4);
            const float wgt = __fdividef(vrow[h], Z);
#pragma unroll
            for (int j = 0; j < 16; j++) oacc[j] = fmaf(wgt, e[j], oacc[j]);
        }

#pragma unroll
        for (int j = 0; j < 16; j++) {
            oacc[j] += __shfl_xor_sync(0xffffffffu, oacc[j], 8);
            oacc[j] += __shfl_xor_sync(0xffffffffu, oacc[j], 16);
        }
        if (g == 0) {
            const int b = blockIdx.x * 32 + bl;
            float* dst = out + (size_t)b * H + r * 4;
#pragma unroll
            for (int w = 0; w < 4; w++) {
                float4 b4 = *(const float4*)(bias + w * 32 + r * 4);
                float4 o;
                o.x = oacc[w*4+0] + b4.x;
                o.y = oacc[w*4+1] + b4.y;
                o.z = oacc[w*4+2] + b4.z;
                o.w = oacc[w*4+3] + b4.w;
                *(float4*)(dst + w * 32) = o;
            }
        }
    }
}

// ---------------------------------------------------------------------------
extern "C" void kernel_launch(void* const* d_in, const int* in_sizes, int n_in,
                              void* d_out, int out_size)
{
    (void)n_in; (void)out_size;
    const float* x    = (const float*)d_in[0];   // [B,2,1024]
    const float* W    = (const float*)d_in[1];   // [128,1024]
    const float* cov  = (const float*)d_in[2];   // [128,128]
    const float* bias = (const float*)d_in[3];   // [128]
    float* out = (float*)d_out;

    const int B = in_sizes[0] / (2 * NE);        // 16384

    prep_w_kernel<<<128, 256>>>(W);

    cudaFuncSetAttribute(fused_kernel,
                         cudaFuncAttributeMaxDynamicSharedMemorySize, FUSED_SMEM);
    fused_kernel<<<(2 * B) / 64, 256, FUSED_SMEM>>>(x, cov, bias, out);
}

// round 15
// speedup vs baseline: 1.2011x; 1.2011x over previous
#include <cuda_runtime.h>
#include <cuda_bf16.h>
#include <cstdint>

#define NE    1024
#define H     128
#define B_MAX 16384

// ---------------------------------------------------------------------------
// Device scratch (no allocation allowed)
// W split into bf16 hi/lo, pre-swizzled SW64 chunk tiles:
// 32 K-chunks, each [128 n-rows x 32 k] bf16 = 128 x 64B = 8192 B.
// ---------------------------------------------------------------------------
__device__ __align__(16) unsigned char g_Whi[32 * 8192];
__device__ __align__(16) unsigned char g_Wlo[32 * 8192];

// ---------------------------------------------------------------------------
__device__ __forceinline__ unsigned smem_u32(const void* p) {
    unsigned a;
    asm("{ .reg .u64 t; cvta.to.shared.u64 t, %1; cvt.u32.u64 %0, t; }"
        : "=r"(a) : "l"(p));
    return a;
}
__device__ __host__ __forceinline__ unsigned sw64(unsigned o) {
    return o ^ ((o >> 3) & 0x30);
}

// split fp32x4 -> bf16 hi (packed u64) + bf16 lo (packed u64)
__device__ __forceinline__ void split4(float4 v, unsigned long long& hi,
                                       unsigned long long& lo) {
    __nv_bfloat162 a = __float22bfloat162_rn(make_float2(v.x, v.y));
    __nv_bfloat162 b = __float22bfloat162_rn(make_float2(v.z, v.w));
    float rx = v.x - __bfloat162float(a.x);
    float ry = v.y - __bfloat162float(a.y);
    float rz = v.z - __bfloat162float(b.x);
    float rw = v.w - __bfloat162float(b.y);
    __nv_bfloat162 c = __float22bfloat162_rn(make_float2(rx, ry));
    __nv_bfloat162 d = __float22bfloat162_rn(make_float2(rz, rw));
    unsigned ua = *reinterpret_cast<unsigned*>(&a);
    unsigned ub = *reinterpret_cast<unsigned*>(&b);
    unsigned uc = *reinterpret_cast<unsigned*>(&c);
    unsigned ud = *reinterpret_cast<unsigned*>(&d);
    hi = (unsigned long long)ua | ((unsigned long long)ub << 32);
    lo = (unsigned long long)uc | ((unsigned long long)ud << 32);
}

#define LDMX4(r0, r1, r2, r3, addr)                                          \
    asm volatile("ldmatrix.sync.aligned.m8n8.x4.shared.b16 {%0,%1,%2,%3}, [%4];" \
                 : "=r"(r0), "=r"(r1), "=r"(r2), "=r"(r3) : "r"(addr))

#define MMA16816(c, a0, a1, a2, a3, b0, b1)                                  \
    asm volatile("mma.sync.aligned.m16n8k16.row.col.f32.bf16.bf16.f32 "      \
                 "{%0,%1,%2,%3}, {%4,%5,%6,%7}, {%8,%9}, {%0,%1,%2,%3};"     \
                 : "+f"((c)[0]), "+f"((c)[1]), "+f"((c)[2]), "+f"((c)[3])    \
                 : "r"(a0), "r"(a1), "r"(a2), "r"(a3), "r"(b0), "r"(b1))

#define CP_ASYNC16(dst, src)                                                 \
    asm volatile("cp.async.cg.shared.global [%0], [%1], 16;"                 \
                 :: "r"(dst), "l"(src))

// ---------------------------------------------------------------------------
// Prep: W [128,1024] fp32 -> g_Whi/g_Wlo SW64-swizzled bf16 chunk tiles
// ---------------------------------------------------------------------------
__global__ void prep_w_kernel(const float* __restrict__ W) {
    int idx = blockIdx.x * 256 + threadIdx.x;   // 0..32767
    int h   = idx >> 8;
    int c4g = idx & 255;
    float4 v = *(const float4*)(W + (size_t)h * NE + c4g * 4);
    unsigned long long hi, lo;
    split4(v, hi, lo);
    int kc = c4g >> 3;          // K-chunk (32 wide)
    int c4 = c4g & 7;           // float4 within chunk
    unsigned dst = (unsigned)kc * 8192u + sw64((unsigned)(h * 64 + c4 * 8));
    *reinterpret_cast<unsigned long long*>(g_Whi + dst) = hi;
    *reinterpret_cast<unsigned long long*>(g_Wlo + dst) = lo;
}

// ---------------------------------------------------------------------------
// Fused kernel, 32-row CTA tile for 3 CTAs/SM WITHOUT spills.
// Phase 1 (GEMM): 32 rows (= 16 b x {values,mask}) x 128 cols via mma.sync,
//   split bf16 (acc += Ahi*Bhi + Ahi*Blo + Alo*Bhi), K chunks of 32,
//   double-buffered cp.async for W, LDG->split->swizzled STS for x.
//   8 warps as 2(m) x 4(n); warp tile 16x32 -> 16 accum regs/thread.
// Phase 2 (head): same CTA consumes its 16 b's from smem:
//   out[b,k] = sum_h values[b,h] * exp(mask[b,h]*cov[h,k]) / Z[b,h] + bias[k]
//   cov cached in smem as bf16, row stride 160 bf16.
//
// SMEM (bytes):
//   [0, 8192)       A staging: 2 stages x (hi 2KB + lo 2KB)
//   [8192, 40960)   B staging: 2 stages x (hi 8KB + lo 8KB)
//   [0, 16896)      reused after mainloop as vm[32][132] fp32
//   [16896, 57856)  cov bf16 [128][stride 160]
// ---------------------------------------------------------------------------
#define FUSED_SMEM 57856
#define VM_PAD 132
#define COVW 80   // cov row stride in 32-bit words (160 bf16)

__global__ __launch_bounds__(256, 3)
void fused_kernel(const float* __restrict__ x, const float* __restrict__ cov,
                  const float* __restrict__ bias, float* __restrict__ out)
{
    extern __shared__ unsigned char sm[];
    float* smf = reinterpret_cast<float*>(sm);
    const unsigned smb = smem_u32(sm);

    const int tid  = threadIdx.x;
    const int wid  = tid >> 5, lane = tid & 31;
    const int warp_m = wid & 1, warp_n = wid >> 1;
    const int m_base = warp_m * 16, n_base = warp_n * 32;
    const int r0 = blockIdx.x * 32;

    // ---- per-lane ldmatrix offsets
    const int lrow8 = (lane & 7) + ((lane >> 3) & 1) * 8;
    const int ksel  = lane >> 4;
    const unsigned aoff0 = sw64((unsigned)((m_base + lrow8) * 64 + ksel * 16));
    const unsigned aoff1 = sw64((unsigned)((m_base + lrow8) * 64 + 32 + ksel * 16));
    unsigned boff[2][2];
#pragma unroll
    for (int p = 0; p < 2; p++) {
        unsigned rb = (unsigned)(n_base + p * 16 + lrow8) * 64 + ksel * 16;
#pragma unroll
        for (int kk = 0; kk < 2; kk++) boff[p][kk] = sw64(rb + kk * 32);
    }

    // ---- x staging map: 1 float4 per thread (32 rows x 8 float4)
    const int xrow = tid >> 3;          // 0..31
    const int xc4  = tid & 7;
    const unsigned asw = sw64((unsigned)(xrow * 64 + xc4 * 8));
    const float* xbase = x + (size_t)(r0 + xrow) * NE + xc4 * 4;

    // ---- W cp.async map: 4 x 16B per thread (hi 2 + lo 2)
    const unsigned wdst0 = (unsigned)(tid * 16);
    const unsigned wdst1 = (unsigned)(tid * 16 + 4096);

    float acc[4][4];
#pragma unroll
    for (int t = 0; t < 4; t++)
#pragma unroll
        for (int j = 0; j < 4; j++) acc[t][j] = 0.f;

    // prologue: W chunk 0 via cp.async, x chunk 0 via LDG
    {
        unsigned bh = smb + 8192, bl = smb + 16384;
        CP_ASYNC16(bh + wdst0, g_Whi + wdst0);
        CP_ASYNC16(bh + wdst1, g_Whi + wdst1);
        CP_ASYNC16(bl + wdst0, g_Wlo + wdst0);
        CP_ASYNC16(bl + wdst1, g_Wlo + wdst1);
        asm volatile("cp.async.commit_group;");
    }
    float4 xv = *(const float4*)xbase;

    for (int kc = 0; kc < 32; kc++) {
        const int s = kc & 1;
        const unsigned Ahi_b = smb + s * 4096;
        const unsigned Alo_b = Ahi_b + 2048;
        const unsigned Bhi_b = smb + 8192 + s * 16384;
        const unsigned Blo_b = Bhi_b + 8192;

        // ---- stage A (x chunk kc) from prefetched regs, swizzled bf16 hi/lo
        {
            unsigned long long hi, lo;
            split4(xv, hi, lo);
            *reinterpret_cast<unsigned long long*>(sm + s * 4096 + asw)        = hi;
            *reinterpret_cast<unsigned long long*>(sm + s * 4096 + 2048 + asw) = lo;
        }

        asm volatile("cp.async.wait_group 0;");
        __syncthreads();

        // ---- issue next chunk's W + x loads
        if (kc < 31) {
            const unsigned char* wh = g_Whi + (size_t)(kc + 1) * 8192;
            const unsigned char* wl = g_Wlo + (size_t)(kc + 1) * 8192;
            unsigned bh = smb + 8192 + (s ^ 1) * 16384, bl = bh + 8192;
            CP_ASYNC16(bh + wdst0, wh + wdst0);
            CP_ASYNC16(bh + wdst1, wh + wdst1);
            CP_ASYNC16(bl + wdst0, wl + wdst0);
            CP_ASYNC16(bl + wdst1, wl + wdst1);
            asm volatile("cp.async.commit_group;");
            xv = *(const float4*)(xbase + (kc + 1) * 32);
        }

        // ldmatrix.x4 on B: m0=n0-7/k0-7, m1=n8-15/k0-7, m2=n0-7/k8-15,
        // m3=n8-15/k8-15 -> mma B pairs (m0,m2) and (m1,m3).
#pragma unroll
        for (int kk = 0; kk < 2; kk++) {
            const unsigned ao = kk ? aoff1 : aoff0;
            unsigned ah0, ah1, ah2, ah3, al0, al1, al2, al3;
            LDMX4(ah0, ah1, ah2, ah3, Ahi_b + ao);
            LDMX4(al0, al1, al2, al3, Alo_b + ao);
#pragma unroll
            for (int p = 0; p < 2; p++) {
                unsigned bh0, bh1, bh2, bh3, bl0, bl1, bl2, bl3;
                LDMX4(bh0, bh1, bh2, bh3, Bhi_b + boff[p][kk]);
                LDMX4(bl0, bl1, bl2, bl3, Blo_b + boff[p][kk]);
                MMA16816(acc[2*p],   ah0, ah1, ah2, ah3, bh0, bh2);
                MMA16816(acc[2*p],   ah0, ah1, ah2, ah3, bl0, bl2);
                MMA16816(acc[2*p],   al0, al1, al2, al3, bh0, bh2);
                MMA16816(acc[2*p+1], ah0, ah1, ah2, ah3, bh1, bh3);
                MMA16816(acc[2*p+1], ah0, ah1, ah2, ah3, bl1, bl3);
                MMA16816(acc[2*p+1], al0, al1, al2, al3, bh1, bh3);
            }
        }
        __syncthreads();
    }

    // ---- epilogue: accums -> vm_s[32][VM_PAD] fp32 (rows: m=2*b_local+s)
    {
        const int gid = lane >> 2, tig = lane & 3;
        const int m0 = m_base + gid, m1 = m0 + 8;
#pragma unroll
        for (int o = 0; o < 4; o++) {
            const int col = n_base + o * 8 + tig * 2;
            *(float2*)(smf + m0 * VM_PAD + col) = make_float2(acc[o][0], acc[o][1]);
            *(float2*)(smf + m1 * VM_PAD + col) = make_float2(acc[o][2], acc[o][3]);
        }
    }

    // ---- load cov -> smem bf16 [128][COVW words] (disjoint from vm_s)
    {
        const float2* cg = (const float2*)cov;                // 8192 float2
        unsigned* cs = (unsigned*)(smf + 32 * VM_PAD);
#pragma unroll 4
        for (int i = tid; i < (H * H) / 2; i += 256) {
            int h = i >> 6, kp = i & 63;
            __nv_bfloat162 bb = __float22bfloat162_rn(cg[i]);
            cs[h * COVW + kp] = *reinterpret_cast<unsigned*>(&bb);
        }
    }
    __syncthreads();

    // ---- head phase: 8 warps x 2 b each (16 b per CTA)
    const unsigned* cov_s = (const unsigned*)(smf + 32 * VM_PAD);
    const int g = lane >> 3;      // h within group of 4
    const int r = lane & 7;       // lane owns k = w*32 + r*4 + t
    const unsigned* crow_base = cov_s + r * 2;

#pragma unroll 1
    for (int i = 0; i < 2; i++) {
        const int bl = wid * 2 + i;
        const float* vrow = smf + (2 * bl) * VM_PAD;       // values row
        const float* mrow = smf + (2 * bl + 1) * VM_PAD;   // mask row

        float oacc[16];
#pragma unroll
        for (int j = 0; j < 16; j++) oacc[j] = 0.f;

        for (int h0 = 0; h0 < H; h0 += 4) {
            const int h = h0 + g;
            const float tm = mrow[h] * 1.4426950408889634f;   // log2(e)
            const unsigned* crow = crow_base + h * COVW;
            float e[16];
            float Z = 0.f;
#pragma unroll
            for (int w = 0; w < 4; w++) {
                uint2 cp = *(const uint2*)(crow + w * 16);
                float c0 = __uint_as_float(cp.x << 16);
                float c1 = __uint_as_float(cp.x & 0xFFFF0000u);
                float c2 = __uint_as_float(cp.y << 16);
                float c3 = __uint_as_float(cp.y & 0xFFFF0000u);
                float e0, e1, e2, e3;
                asm("ex2.approx.ftz.f32 %0, %1;" : "=f"(e0) : "f"(tm * c0));
                asm("ex2.approx.ftz.f32 %0, %1;" : "=f"(e1) : "f"(tm * c1));
                asm("ex2.approx.ftz.f32 %0, %1;" : "=f"(e2) : "f"(tm * c2));
                asm("ex2.approx.ftz.f32 %0, %1;" : "=f"(e3) : "f"(tm * c3));
                e[w*4+0] = e0; e[w*4+1] = e1; e[w*4+2] = e2; e[w*4+3] = e3;
                Z += (e0 + e1) + (e2 + e3);
            }
            Z += __shfl_xor_sync(0xffffffffu, Z, 1);
            Z += __shfl_xor_sync(0xffffffffu, Z, 2);
            Z += __shfl_xor_sync(0xffffffffu, Z, 4);
            const float wgt = __fdividef(vrow[h], Z);
#pragma unroll
            for (int j = 0; j < 16; j++) oacc[j] = fmaf(wgt, e[j], oacc[j]);
        }

#pragma unroll
        for (int j = 0; j < 16; j++) {
            oacc[j] += __shfl_xor_sync(0xffffffffu, oacc[j], 8);
            oacc[j] += __shfl_xor_sync(0xffffffffu, oacc[j], 16);
        }
        if (g == 0) {
            const int b = blockIdx.x * 16 + bl;
            float* dst = out + (size_t)b * H + r * 4;
#pragma unroll
            for (int w = 0; w < 4; w++) {
                float4 b4 = *(const float4*)(bias + w * 32 + r * 4);
                float4 o;
                o.x = oacc[w*4+0] + b4.x;
                o.y = oacc[w*4+1] + b4.y;
                o.z = oacc[w*4+2] + b4.z;
                o.w = oacc[w*4+3] + b4.w;
                *(float4*)(dst + w * 32) = o;
            }
        }
    }
}

// ---------------------------------------------------------------------------
extern "C" void kernel_launch(void* const* d_in, const int* in_sizes, int n_in,
                              void* d_out, int out_size)
{
    (void)n_in; (void)out_size;
    const float* x    = (const float*)d_in[0];   // [B,2,1024]
    const float* W    = (const float*)d_in[1];   // [128,1024]
    const float* cov  = (const float*)d_in[2];   // [128,128]
    const float* bias = (const float*)d_in[3];   // [128]
    float* out = (float*)d_out;

    const int B = in_sizes[0] / (2 * NE);        // 16384

    prep_w_kernel<<<128, 256>>>(W);

    cudaFuncSetAttribute(fused_kernel,
                         cudaFuncAttributeMaxDynamicSharedMemorySize, FUSED_SMEM);
    fused_kernel<<<(2 * B) / 32, 256, FUSED_SMEM>>>(x, cov, bias, out);
}

// round 17
// speedup vs baseline: 1.3095x; 1.0902x over previous
#include <cuda_runtime.h>
#include <cuda_bf16.h>
#include <cuda_fp16.h>
#include <cstdint>

#define NE    1024
#define H     128
#define B_MAX 16384

// ---------------------------------------------------------------------------
// Device scratch (no allocation allowed)
// W split into fp16 hi/lo, pre-swizzled SW64 chunk tiles:
// 32 K-chunks, each [128 n-rows x 32 k] fp16 = 128 x 64B = 8192 B.
// ---------------------------------------------------------------------------
__device__ __align__(16) unsigned char g_Whi[32 * 8192];
__device__ __align__(16) unsigned char g_Wlo[32 * 8192];

// ---------------------------------------------------------------------------
__device__ __forceinline__ unsigned smem_u32(const void* p) {
    unsigned a;
    asm("{ .reg .u64 t; cvta.to.shared.u64 t, %1; cvt.u32.u64 %0, t; }"
        : "=r"(a) : "l"(p));
    return a;
}
__device__ __host__ __forceinline__ unsigned sw64(unsigned o) {
    return o ^ ((o >> 3) & 0x30);
}

// split fp32x4 -> fp16 hi (packed u64) + fp16 lo (packed u64)
__device__ __forceinline__ void split4h(float4 v, unsigned long long& hi,
                                        unsigned long long& lo) {
    __half2 a = __float22half2_rn(make_float2(v.x, v.y));
    __half2 b = __float22half2_rn(make_float2(v.z, v.w));
    float rx = v.x - __half2float(__low2half(a));
    float ry = v.y - __half2float(__high2half(a));
    float rz = v.z - __half2float(__low2half(b));
    float rw = v.w - __half2float(__high2half(b));
    __half2 c = __float22half2_rn(make_float2(rx, ry));
    __half2 d = __float22half2_rn(make_float2(rz, rw));
    unsigned ua = *reinterpret_cast<unsigned*>(&a);
    unsigned ub = *reinterpret_cast<unsigned*>(&b);
    unsigned uc = *reinterpret_cast<unsigned*>(&c);
    unsigned ud = *reinterpret_cast<unsigned*>(&d);
    hi = (unsigned long long)ua | ((unsigned long long)ub << 32);
    lo = (unsigned long long)uc | ((unsigned long long)ud << 32);
}

// fp32x4 -> fp16x4 (packed u64), plain round-to-nearest
__device__ __forceinline__ unsigned long long cvt4h(float4 v) {
    __half2 a = __float22half2_rn(make_float2(v.x, v.y));
    __half2 b = __float22half2_rn(make_float2(v.z, v.w));
    unsigned ua = *reinterpret_cast<unsigned*>(&a);
    unsigned ub = *reinterpret_cast<unsigned*>(&b);
    return (unsigned long long)ua | ((unsigned long long)ub << 32);
}

#define LDMX4(r0, r1, r2, r3, addr)                                          \
    asm volatile("ldmatrix.sync.aligned.m8n8.x4.shared.b16 {%0,%1,%2,%3}, [%4];" \
                 : "=r"(r0), "=r"(r1), "=r"(r2), "=r"(r3) : "r"(addr))

#define MMA16816(c, a0, a1, a2, a3, b0, b1)                                  \
    asm volatile("mma.sync.aligned.m16n8k16.row.col.f32.f16.f16.f32 "        \
                 "{%0,%1,%2,%3}, {%4,%5,%6,%7}, {%8,%9}, {%0,%1,%2,%3};"     \
                 : "+f"((c)[0]), "+f"((c)[1]), "+f"((c)[2]), "+f"((c)[3])    \
                 : "r"(a0), "r"(a1), "r"(a2), "r"(a3), "r"(b0), "r"(b1))

#define CP_ASYNC16(dst, src)                                                 \
    asm volatile("cp.async.cg.shared.global [%0], [%1], 16;"                 \
                 :: "r"(dst), "l"(src))

// ---------------------------------------------------------------------------
// Prep: W [128,1024] fp32 -> g_Whi/g_Wlo SW64-swizzled fp16 split chunk tiles
// ---------------------------------------------------------------------------
__global__ void prep_w_kernel(const float* __restrict__ W) {
    int idx = blockIdx.x * 256 + threadIdx.x;   // 0..32767
    int h   = idx >> 8;
    int c4g = idx & 255;
    float4 v = *(const float4*)(W + (size_t)h * NE + c4g * 4);
    unsigned long long hi, lo;
    split4h(v, hi, lo);
    int kc = c4g >> 3;          // K-chunk (32 wide)
    int c4 = c4g & 7;           // float4 within chunk
    unsigned dst = (unsigned)kc * 8192u + sw64((unsigned)(h * 64 + c4 * 8));
    *reinterpret_cast<unsigned long long*>(g_Whi + dst) = hi;
    *reinterpret_cast<unsigned long long*>(g_Wlo + dst) = lo;
}

// ---------------------------------------------------------------------------
// Fused kernel, 32-row CTA tile, fp16 2-product GEMM.
// Phase 1 (GEMM): 32 rows (= 16 b x {values,mask}) x 128 cols via mma.sync,
//   acc += A*Bhi + A*Blo, A = fp16(x) unsplit, B = W fp16 hi/lo.
//   K chunks of 32, double-buffered cp.async for W, LDG->cvt->STS for x.
//   8 warps as 2(m) x 4(n); warp tile 16x32 -> 16 accum regs/thread.
// Phase 2 (head): same CTA consumes its 16 b's from smem:
//   out[b,k] = sum_h values[b,h] * exp(mask[b,h]*cov[h,k]) / Z[b,h] + bias[k]
//   cov cached in smem as bf16, row stride 160 bf16 (conflict-free phases).
//
// SMEM (bytes):
//   [0, 4096)       A staging: 2 stages x 2KB (fp16 32x32)
//   [4096, 36864)   B staging: 2 stages x (hi 8KB + lo 8KB)
//   [0, 16896)      reused after mainloop as vm[32][132] fp32
//   [16896, 57856)  cov bf16 [128][stride 160]
// ---------------------------------------------------------------------------
#define FUSED_SMEM 57856
#define VM_PAD 132
#define COVW 80   // cov row stride in 32-bit words (160 bf16)

__global__ __launch_bounds__(256, 3)
void fused_kernel(const float* __restrict__ x, const float* __restrict__ cov,
                  const float* __restrict__ bias, float* __restrict__ out)
{
    extern __shared__ unsigned char sm[];
    float* smf = reinterpret_cast<float*>(sm);
    const unsigned smb = smem_u32(sm);

    const int tid  = threadIdx.x;
    const int wid  = tid >> 5, lane = tid & 31;
    const int warp_m = wid & 1, warp_n = wid >> 1;
    const int m_base = warp_m * 16, n_base = warp_n * 32;
    const int r0 = blockIdx.x * 32;

    // ---- per-lane ldmatrix offsets
    const int lrow8 = (lane & 7) + ((lane >> 3) & 1) * 8;
    const int ksel  = lane >> 4;
    const unsigned aoff0 = sw64((unsigned)((m_base + lrow8) * 64 + ksel * 16));
    const unsigned aoff1 = sw64((unsigned)((m_base + lrow8) * 64 + 32 + ksel * 16));
    unsigned boff[2][2];
#pragma unroll
    for (int p = 0; p < 2; p++) {
        unsigned rb = (unsigned)(n_base + p * 16 + lrow8) * 64 + ksel * 16;
#pragma unroll
        for (int kk = 0; kk < 2; kk++) boff[p][kk] = sw64(rb + kk * 32);
    }

    // ---- x staging map: 1 float4 per thread (32 rows x 8 float4)
    const int xrow = tid >> 3;          // 0..31
    const int xc4  = tid & 7;
    const unsigned asw = sw64((unsigned)(xrow * 64 + xc4 * 8));
    const float* xbase = x + (size_t)(r0 + xrow) * NE + xc4 * 4;

    // ---- W cp.async map: 4 x 16B per thread (hi 2 + lo 2)
    const unsigned wdst0 = (unsigned)(tid * 16);
    const unsigned wdst1 = (unsigned)(tid * 16 + 4096);

    float acc[4][4];
#pragma unroll
    for (int t = 0; t < 4; t++)
#pragma unroll
        for (int j = 0; j < 4; j++) acc[t][j] = 0.f;

    // prologue: W chunk 0 via cp.async, x chunk 0 via LDG
    {
        unsigned bh = smb + 4096, bl = smb + 12288;
        CP_ASYNC16(bh + wdst0, g_Whi + wdst0);
        CP_ASYNC16(bh + wdst1, g_Whi + wdst1);
        CP_ASYNC16(bl + wdst0, g_Wlo + wdst0);
        CP_ASYNC16(bl + wdst1, g_Wlo + wdst1);
        asm volatile("cp.async.commit_group;");
    }
    float4 xv = *(const float4*)xbase;

    for (int kc = 0; kc < 32; kc++) {
        const int s = kc & 1;
        const unsigned A_b   = smb + s * 2048;
        const unsigned Bhi_b = smb + 4096 + s * 16384;
        const unsigned Blo_b = Bhi_b + 8192;

        // ---- stage A (x chunk kc) from prefetched regs: fp16, swizzled
        *reinterpret_cast<unsigned long long*>(sm + s * 2048 + asw) = cvt4h(xv);

        asm volatile("cp.async.wait_group 0;");
        __syncthreads();

        // ---- issue next chunk's W + x loads
        if (kc < 31) {
            const unsigned char* wh = g_Whi + (size_t)(kc + 1) * 8192;
            const unsigned char* wl = g_Wlo + (size_t)(kc + 1) * 8192;
            unsigned bh = smb + 4096 + (s ^ 1) * 16384, bl = bh + 8192;
            CP_ASYNC16(bh + wdst0, wh + wdst0);
            CP_ASYNC16(bh + wdst1, wh + wdst1);
            CP_ASYNC16(bl + wdst0, wl + wdst0);
            CP_ASYNC16(bl + wdst1, wl + wdst1);
            asm volatile("cp.async.commit_group;");
            xv = *(const float4*)(xbase + (kc + 1) * 32);
        }

        // ldmatrix.x4 on B: m0=n0-7/k0-7, m1=n8-15/k0-7, m2=n0-7/k8-15,
        // m3=n8-15/k8-15 -> mma B pairs (m0,m2) and (m1,m3).
#pragma unroll
        for (int kk = 0; kk < 2; kk++) {
            const unsigned ao = kk ? aoff1 : aoff0;
            unsigned a0, a1, a2, a3;
            LDMX4(a0, a1, a2, a3, A_b + ao);
#pragma unroll
            for (int p = 0; p < 2; p++) {
                unsigned bh0, bh1, bh2, bh3, bl0, bl1, bl2, bl3;
                LDMX4(bh0, bh1, bh2, bh3, Bhi_b + boff[p][kk]);
                LDMX4(bl0, bl1, bl2, bl3, Blo_b + boff[p][kk]);
                MMA16816(acc[2*p],   a0, a1, a2, a3, bh0, bh2);
                MMA16816(acc[2*p],   a0, a1, a2, a3, bl0, bl2);
                MMA16816(acc[2*p+1], a0, a1, a2, a3, bh1, bh3);
                MMA16816(acc[2*p+1], a0, a1, a2, a3, bl1, bl3);
            }
        }
        __syncthreads();
    }

    // ---- epilogue: accums -> vm_s[32][VM_PAD] fp32 (rows: m=2*b_local+s)
    {
        const int gid = lane >> 2, tig = lane & 3;
        const int m0 = m_base + gid, m1 = m0 + 8;
#pragma unroll
        for (int o = 0; o < 4; o++) {
            const int col = n_base + o * 8 + tig * 2;
            *(float2*)(smf + m0 * VM_PAD + col) = make_float2(acc[o][0], acc[o][1]);
            *(float2*)(smf + m1 * VM_PAD + col) = make_float2(acc[o][2], acc[o][3]);
        }
    }

    // ---- load cov -> smem bf16 [128][COVW words] (disjoint from vm_s)
    {
        const float2* cg = (const float2*)cov;                // 8192 float2
        unsigned* cs = (unsigned*)(smf + 32 * VM_PAD);
#pragma unroll 4
        for (int i = tid; i < (H * H) / 2; i += 256) {
            int h = i >> 6, kp = i & 63;
            __nv_bfloat162 bb = __float22bfloat162_rn(cg[i]);
            cs[h * COVW + kp] = *reinterpret_cast<unsigned*>(&bb);
        }
    }
    __syncthreads();

    // ---- head phase: 8 warps x 2 b each (16 b per CTA)
    const unsigned* cov_s = (const unsigned*)(smf + 32 * VM_PAD);
    const int g = lane >> 3;      // h within group of 4
    const int r = lane & 7;       // lane owns k = w*32 + r*4 + t
    const unsigned* crow_base = cov_s + r * 2;

#pragma unroll 1
    for (int i = 0; i < 2; i++) {
        const int bl = wid * 2 + i;
        const float* vrow = smf + (2 * bl) * VM_PAD;       // values row
        const float* mrow = smf + (2 * bl + 1) * VM_PAD;   // mask row

        float oacc[16];
#pragma unroll
        for (int j = 0; j < 16; j++) oacc[j] = 0.f;

        for (int h0 = 0; h0 < H; h0 += 4) {
            const int h = h0 + g;
            const float tm = mrow[h] * 1.4426950408889634f;   // log2(e)
            const unsigned* crow = crow_base + h * COVW;
            float e[16];
            float Z = 0.f;
#pragma unroll
            for (int w = 0; w < 4; w++) {
                uint2 cp = *(const uint2*)(crow + w * 16);
                float c0 = __uint_as_float(cp.x << 16);
                float c1 = __uint_as_float(cp.x & 0xFFFF0000u);
                float c2 = __uint_as_float(cp.y << 16);
                float c3 = __uint_as_float(cp.y & 0xFFFF0000u);
                float e0, e1, e2, e3;
                asm("ex2.approx.ftz.f32 %0, %1;" : "=f"(e0) : "f"(tm * c0));
                asm("ex2.approx.ftz.f32 %0, %1;" : "=f"(e1) : "f"(tm * c1));
                asm("ex2.approx.ftz.f32 %0, %1;" : "=f"(e2) : "f"(tm * c2));
                asm("ex2.approx.ftz.f32 %0, %1;" : "=f"(e3) : "f"(tm * c3));
                e[w*4+0] = e0; e[w*4+1] = e1; e[w*4+2] = e2; e[w*4+3] = e3;
                Z += (e0 + e1) + (e2 + e3);
            }
            Z += __shfl_xor_sync(0xffffffffu, Z, 1);
            Z += __shfl_xor_sync(0xffffffffu, Z, 2);
            Z += __shfl_xor_sync(0xffffffffu, Z, 4);
            const float wgt = __fdividef(vrow[h], Z);
#pragma unroll
            for (int j = 0; j < 16; j++) oacc[j] = fmaf(wgt, e[j], oacc[j]);
        }

#pragma unroll
        for (int j = 0; j < 16; j++) {
            oacc[j] += __shfl_xor_sync(0xffffffffu, oacc[j], 8);
            oacc[j] += __shfl_xor_sync(0xffffffffu, oacc[j], 16);
        }
        if (g == 0) {
            const int b = blockIdx.x * 16 + bl;
            float* dst = out + (size_t)b * H + r * 4;
#pragma unroll
            for (int w = 0; w < 4; w++) {
                float4 b4 = *(const float4*)(bias + w * 32 + r * 4);
                float4 o;
                o.x = oacc[w*4+0] + b4.x;
                o.y = oacc[w*4+1] + b4.y;
                o.z = oacc[w*4+2] + b4.z;
                o.w = oacc[w*4+3] + b4.w;
                *(float4*)(dst + w * 32) = o;
            }
        }
    }
}

// ---------------------------------------------------------------------------
extern "C" void kernel_launch(void* const* d_in, const int* in_sizes, int n_in,
                              void* d_out, int out_size)
{
    (void)n_in; (void)out_size;
    const float* x    = (const float*)d_in[0];   // [B,2,1024]
    const float* W    = (const float*)d_in[1];   // [128,1024]
    const float* cov  = (const float*)d_in[2];   // [128,128]
    const float* bias = (const float*)d_in[3];   // [128]
    float* out = (float*)d_out;

    const int B = in_sizes[0] / (2 * NE);        // 16384

    prep_w_kernel<<<128, 256>>>(W);

    cudaFuncSetAttribute(fused_kernel,
                         cudaFuncAttributeMaxDynamicSharedMemorySize, FUSED_SMEM);
    fused_kernel<<<(2 * B) / 32, 256, FUSED_SMEM>>>(x, cov, bias, out);
}